// round 3
// baseline (speedup 1.0000x reference)
#include <cuda_runtime.h>
#include <math.h>

#define N_ATOMS 512
#define NQC     8
#define NT      16      // targets per block
#define NS      16      // sources per chunk
#define NCH     32      // source chunks
#define TPB     128     // NT * NQC
#define NTQ     (N_ATOMS * NQC)   // 4096

// partial accumulators: [18][chunk][tq]  (9.4 MB, L2-resident)
__device__ float g_partial[18 * NCH * NTQ];

__global__ __launch_bounds__(TPB)
void pairs_kernel(const float* __restrict__ gq, const float* __restrict__ gr,
                  const float* __restrict__ gu, const float* __restrict__ gQ,
                  float* __restrict__ out)
{
    __shared__ __align__(16) float s_sr[NS * 3];
    __shared__ __align__(16) float s_tr[NT * 3];
    __shared__ __align__(16) float s_q [NS * NQC];          // 512 B
    __shared__ __align__(16) float s_u [NS * NQC * 4];      // 2 KB (stride-4 pad)
    __shared__ __align__(16) float s_Q [NS * NQC * 12];     // 6 KB (stride-12 pad)
    __shared__ __align__(16) float s_pair[NS * NT * 8];     // 8 KB {g,c1,c2,c3,c4,dx,dy,dz}

    const int tid = threadIdx.x;
    const int t0  = blockIdx.x * NT;
    const int s0  = blockIdx.y * NS;
    const int ch  = blockIdx.y;

    if (blockIdx.x == 0 && blockIdx.y == 0 && tid == 0)
        out[0] = 0.0f;   // pot accumulator, consumed by finalize after this grid completes

    // ---- phase 1: stage source + target data into smem ----
    for (int i = tid; i < NS * 3; i += TPB) s_sr[i] = gr[s0 * 3 + i];
    for (int i = tid; i < NT * 3; i += TPB) s_tr[i] = gr[t0 * 3 + i];
    {
        const float4* src = (const float4*)(gq + s0 * NQC);
        float4* dst = (float4*)s_q;
        for (int i = tid; i < NS * NQC / 4; i += TPB) dst[i] = src[i];
    }
    for (int i = tid; i < NS * NQC; i += TPB) {
        const float* up = gu + (s0 * NQC + i) * 3;
        s_u[i * 4 + 0] = up[0]; s_u[i * 4 + 1] = up[1]; s_u[i * 4 + 2] = up[2];
    }
    for (int i = tid; i < NS * NQC; i += TPB) {
        const float* Qp = gQ + (s0 * NQC + i) * 9;
#pragma unroll
        for (int k = 0; k < 9; k++) s_Q[i * 12 + k] = Qp[k];
    }
    __syncthreads();

    // ---- phase 2: pair scalar kernels (g, D1..D4)*nc and displacement ----
    const float A_ERF = 0.70710678118654752f;                         // 1/sqrt(2)
    const float NCE = (float)(90.4756 / (2.0 * 3.14159265358979323846));
    const float NCG = (float)((90.4756 / (2.0 * 3.14159265358979323846))
                              * 0.79788456080286536);                 // nc * 2a/sqrt(pi)

#pragma unroll
    for (int p = tid; p < NS * NT; p += TPB) {
        const int s  = p >> 4;
        const int tl = p & 15;
        float dx = s_tr[tl * 3 + 0] - s_sr[s * 3 + 0];
        float dy = s_tr[tl * 3 + 1] - s_sr[s * 3 + 1];
        float dz = s_tr[tl * 3 + 2] - s_sr[s * 3 + 2];
        float g = 0.f, c1 = 0.f, c2 = 0.f, c3 = 0.f, c4 = 0.f;
        if (t0 + tl != s0 + s) {
            float r2 = dx * dx + dy * dy + dz * dz;
            float rr = sqrtf(r2);
            float E  = NCE * erff(A_ERF * rr);
            float G  = NCG * expf(-0.5f * rr * rr);
            float ir = 1.0f / rr;
            float ir2 = ir * ir,  ir3 = ir2 * ir,  ir4 = ir2 * ir2, ir5 = ir4 * ir;
            float ir6 = ir4 * ir2, ir7 = ir6 * ir, ir8 = ir4 * ir4, ir9 = ir8 * ir;
            g  = E * ir;
            c1 = G * ir2 - E * ir3;
            c2 = 3.0f * E * ir5 - 3.0f * G * ir4 - G * ir2;                       // 2*a2 = 1
            c3 = -15.0f * E * ir7 + 15.0f * G * ir6 + 5.0f * G * ir4 + G * ir2;   // 10*a2=5, 4*a2^2=1
            c4 = 105.0f * E * ir9 - 105.0f * G * ir8 - 35.0f * G * ir6
                 - 7.0f * G * ir4 - G * ir2;                                      // 70a2=35, 28a2^2=7, 8a2^3=1
        }
        float4* op = (float4*)&s_pair[p * 8];
        op[0] = make_float4(g, c1, c2, c3);
        op[1] = make_float4(c4, dx, dy, dz);
    }
    __syncthreads();

    // ---- phase 3: per-(target, channel) accumulation over the source tile ----
    const int tl = tid >> 3;
    const int qc = tid & 7;

    float A0 = 0.f, A1 = 0.f, A2 = 0.f;
    float Eux = 0.f, Euy = 0.f, Euz = 0.f;
    float EQx = 0.f, EQy = 0.f, EQz = 0.f;
    float Efx = 0.f, Efy = 0.f, Efz = 0.f;
    float Qxx = 0.f, Qxy = 0.f, Qxz = 0.f, Qyy = 0.f, Qyz = 0.f, Qzz = 0.f;

#pragma unroll 4
    for (int s = 0; s < NS; s++) {
        const float4 pa = *(const float4*)&s_pair[(s * NT + tl) * 8];
        const float4 pb = *(const float4*)&s_pair[(s * NT + tl) * 8 + 4];
        const float g  = pa.x, c1 = pa.y, c2 = pa.z, c3 = pa.w;
        const float c4 = pb.x, dx = pb.y, dy = pb.z, dz = pb.w;
        const float qs = s_q[s * NQC + qc];
        const float4 uv = *(const float4*)&s_u[(s * NQC + qc) * 4];
        const float ux = uv.x, uy = uv.y, uz = uv.z;
        const float4 qa = *(const float4*)&s_Q[(s * NQC + qc) * 12];
        const float4 qb = *(const float4*)&s_Q[(s * NQC + qc) * 12 + 4];
        const float4 qcv= *(const float4*)&s_Q[(s * NQC + qc) * 12 + 8];
        const float Q00 = qa.x, Q01 = qa.y, Q02 = qa.z;
        const float Q10 = qa.w, Q11 = qb.x, Q12 = qb.y;
        const float Q20 = qb.z, Q21 = qb.w, Q22 = qcv.x;

        const float ud  = fmaf(ux, dx, fmaf(uy, dy, uz * dz));
        const float Qdx = fmaf(Q00, dx, fmaf(Q01, dy, Q02 * dz));
        const float Qdy = fmaf(Q10, dx, fmaf(Q11, dy, Q12 * dz));
        const float Qdz = fmaf(Q20, dx, fmaf(Q21, dy, Q22 * dz));
        const float Qtx = fmaf(Q00, dx, fmaf(Q10, dy, Q20 * dz));
        const float Qty = fmaf(Q01, dx, fmaf(Q11, dy, Q21 * dz));
        const float Qtz = fmaf(Q02, dx, fmaf(Q12, dy, Q22 * dz));
        const float trq = Q00 + Q11 + Q22;
        const float dQd = fmaf(dx, Qdx, fmaf(dy, Qdy, dz * Qdz));
        const float sx = Qdx + Qtx, sy = Qdy + Qty, sz = Qdz + Qtz;

        // potentials at target
        A0 = fmaf(g, qs, A0);
        A1 = fmaf(-c1, ud, A1);
        A2 = fmaf(0.5f * c2, dQd, A2);
        A2 = fmaf(0.5f * c1, trq, A2);

        // E_u (dipole field)
        const float t2u = c2 * ud;
        Eux = fmaf(t2u, dx, fmaf(c1, ux, Eux));
        Euy = fmaf(t2u, dy, fmaf(c1, uy, Euy));
        Euz = fmaf(t2u, dz, fmaf(c1, uz, Euz));

        // E_Q (quadrupole field)
        const float Aq = -0.5f * fmaf(c3, dQd, c2 * trq);
        const float Bq = -0.5f * c2;
        EQx = fmaf(Aq, dx, fmaf(Bq, sx, EQx));
        EQy = fmaf(Aq, dy, fmaf(Bq, sy, EQy));
        EQz = fmaf(Aq, dz, fmaf(Bq, sz, EQz));

        // field from charges
        const float t1q = c1 * qs;
        Efx = fmaf(-t1q, dx, Efx);
        Efy = fmaf(-t1q, dy, Efy);
        Efz = fmaf(-t1q, dz, Efz);

        // QQ (symmetric 3x3)
        const float cA = fmaf(c4, dQd, c3 * trq);
        const float cD = fmaf(c3, dQd, c2 * trq);
        const float hx = c3 * sx, hy = c3 * sy, hz = c3 * sz;
        Qxx = fmaf(cA, dx * dx, Qxx);
        Qxx = fmaf(hx + hx, dx, Qxx);
        Qxx = fmaf(c2, Q00 + Q00, Qxx + cD);
        Qyy = fmaf(cA, dy * dy, Qyy);
        Qyy = fmaf(hy + hy, dy, Qyy);
        Qyy = fmaf(c2, Q11 + Q11, Qyy + cD);
        Qzz = fmaf(cA, dz * dz, Qzz);
        Qzz = fmaf(hz + hz, dz, Qzz);
        Qzz = fmaf(c2, Q22 + Q22, Qzz + cD);
        Qxy = fmaf(cA, dx * dy, Qxy);
        Qxy = fmaf(hx, dy, Qxy);
        Qxy = fmaf(hy, dx, Qxy);
        Qxy = fmaf(c2, Q01 + Q10, Qxy);
        Qxz = fmaf(cA, dx * dz, Qxz);
        Qxz = fmaf(hx, dz, Qxz);
        Qxz = fmaf(hz, dx, Qxz);
        Qxz = fmaf(c2, Q02 + Q20, Qxz);
        Qyz = fmaf(cA, dy * dz, Qyz);
        Qyz = fmaf(hy, dz, Qyz);
        Qyz = fmaf(hz, dy, Qyz);
        Qyz = fmaf(c2, Q12 + Q21, Qyz);
    }

    // ---- write partials (coalesced across threads for each k) ----
    const int tqi  = (t0 + tl) * NQC + qc;
    const int base = ch * NTQ + tqi;
    const float acc[18] = {A0, A1, A2, Eux, Euy, Euz, EQx, EQy, EQz,
                           Efx, Efy, Efz, Qxx, Qxy, Qxz, Qyy, Qyz, Qzz};
#pragma unroll
    for (int k = 0; k < 18; k++)
        g_partial[k * (NCH * NTQ) + base] = acc[k];
}

__global__ __launch_bounds__(256)
void finalize_kernel(const float* __restrict__ gq, const float* __restrict__ gu,
                     const float* __restrict__ gQ, const float* __restrict__ gkap,
                     const float* __restrict__ gal, float* __restrict__ out)
{
    const int tqi = blockIdx.x * 256 + threadIdx.x;

    float acc[18];
#pragma unroll
    for (int k = 0; k < 18; k++) {
        float s = 0.f;
#pragma unroll
        for (int c = 0; c < NCH; c++)
            s += g_partial[k * (NCH * NTQ) + c * NTQ + tqi];
        acc[k] = s;
    }
    const float A0 = acc[0], A1 = acc[1], A2 = acc[2];
    const float Eux = acc[3], Euy = acc[4], Euz = acc[5];
    const float EQx = acc[6], EQy = acc[7], EQz = acc[8];
    const float Efx = acc[9], Efy = acc[10], Efz = acc[11];
    const float Qxx = acc[12], Qxy = acc[13], Qxz = acc[14];
    const float Qyy = acc[15], Qyz = acc[16], Qzz = acc[17];

    const float qv  = gq[tqi];
    const float kap = gkap[tqi];
    const float al  = gal[tqi];
    const float ux = gu[tqi * 3 + 0], uy = gu[tqi * 3 + 1], uz = gu[tqi * 3 + 2];
    const float* Qp = gQ + tqi * 9;

    const float ephi = A0 + A1 + A2;
    out[1 + tqi] = -kap * ephi;                               // q_induced

    const float ex = Efx + Eux + EQx;
    const float ey = Efy + Euy + EQy;
    const float ez = Efz + Euz + EQz;
    out[1 + NTQ + tqi * 3 + 0] = al * ex;                     // u_induced
    out[1 + NTQ + tqi * 3 + 1] = al * ey;
    out[1 + NTQ + tqi * 3 + 2] = al * ez;

    const float qQQ = Qp[0] * Qxx + Qp[4] * Qyy + Qp[8] * Qzz
                    + (Qp[1] + Qp[3]) * Qxy + (Qp[2] + Qp[6]) * Qxz
                    + (Qp[5] + Qp[7]) * Qyz;
    const float uEu = ux * Eux + uy * Euy + uz * Euz;
    const float uEQ = ux * EQx + uy * EQy + uz * EQz;
    const float e2  = ex * ex + ey * ey + ez * ez;

    float pot = 0.5f * A0 * qv + A1 * qv - 0.5f * uEu + qv * A2
              + 0.125f * qQQ - uEQ
              - 0.5f * kap * ephi * ephi
              - 0.5f * al * e2;

    __shared__ float red[256];
    red[threadIdx.x] = pot;
    __syncthreads();
    for (int off = 128; off > 0; off >>= 1) {
        if (threadIdx.x < off) red[threadIdx.x] += red[threadIdx.x + off];
        __syncthreads();
    }
    if (threadIdx.x == 0) atomicAdd(&out[0], red[0]);
}

extern "C" void kernel_launch(void* const* d_in, const int* in_sizes, int n_in,
                              void* d_out, int out_size)
{
    (void)in_sizes; (void)n_in; (void)out_size;
    const float* q     = (const float*)d_in[0];
    const float* r     = (const float*)d_in[1];
    // d_in[2] = cell (zero -> realspace branch), d_in[3] = batch (single graph): unused
    const float* u     = (const float*)d_in[4];
    const float* quad  = (const float*)d_in[5];
    const float* kappa = (const float*)d_in[6];
    const float* alpha = (const float*)d_in[7];
    float* out = (float*)d_out;

    pairs_kernel<<<dim3(N_ATOMS / NT, NCH), TPB>>>(q, r, u, quad, out);
    finalize_kernel<<<NTQ / 256, 256>>>(q, u, quad, kappa, alpha, out);
}

// round 4
// speedup vs baseline: 1.7614x; 1.7614x over previous
#include <cuda_runtime.h>
#include <math.h>

#define N_ATOMS 512
#define NQC     8
#define NT      16      // targets per block
#define NS      16      // sources per chunk
#define NCH     32      // source chunks
#define TPB     128     // NT * NQC
#define NTQ     (N_ATOMS * NQC)   // 4096

// compact accumulators: [18][tq] (288 KB, L2-resident).
// Zero at process start (static init); finalize re-zeroes after reading,
// so every kernel_launch invocation sees a clean array.
__device__ float g_acc[18 * NTQ];

__global__ __launch_bounds__(TPB)
void pairs_kernel(const float* __restrict__ gq, const float* __restrict__ gr,
                  const float* __restrict__ gu, const float* __restrict__ gQ,
                  float* __restrict__ out)
{
    __shared__ __align__(16) float s_sr[NS * 3];
    __shared__ __align__(16) float s_tr[NT * 3];
    __shared__ __align__(16) float s_q [NS * NQC];          // 512 B
    __shared__ __align__(16) float s_u [NS * NQC * 4];      // 2 KB (stride-4 pad)
    __shared__ __align__(16) float s_Q [NS * NQC * 12];     // 6 KB (stride-12 pad)
    __shared__ __align__(16) float s_pair[NS * NT * 8];     // 8 KB {g,c1,c2,c3,c4,dx,dy,dz}

    const int tid = threadIdx.x;
    const int t0  = blockIdx.x * NT;
    const int s0  = blockIdx.y * NS;

    if (blockIdx.x == 0 && blockIdx.y == 0 && tid == 0)
        out[0] = 0.0f;   // pot accumulator, consumed by finalize after this grid completes

    // ---- phase 1: stage source + target data into smem ----
    for (int i = tid; i < NS * 3; i += TPB) s_sr[i] = gr[s0 * 3 + i];
    for (int i = tid; i < NT * 3; i += TPB) s_tr[i] = gr[t0 * 3 + i];
    {
        const float4* src = (const float4*)(gq + s0 * NQC);
        float4* dst = (float4*)s_q;
        for (int i = tid; i < NS * NQC / 4; i += TPB) dst[i] = src[i];
    }
    for (int i = tid; i < NS * NQC; i += TPB) {
        const float* up = gu + (s0 * NQC + i) * 3;
        s_u[i * 4 + 0] = up[0]; s_u[i * 4 + 1] = up[1]; s_u[i * 4 + 2] = up[2];
    }
    for (int i = tid; i < NS * NQC; i += TPB) {
        const float* Qp = gQ + (s0 * NQC + i) * 9;
#pragma unroll
        for (int k = 0; k < 9; k++) s_Q[i * 12 + k] = Qp[k];
    }
    __syncthreads();

    // ---- phase 2: pair scalar kernels (g, D1..D4)*nc and displacement ----
    const float A_ERF = 0.70710678118654752f;                         // 1/sqrt(2)
    const float NCE = (float)(90.4756 / (2.0 * 3.14159265358979323846));
    const float NCG = (float)((90.4756 / (2.0 * 3.14159265358979323846))
                              * 0.79788456080286536);                 // nc * 2a/sqrt(pi)

#pragma unroll
    for (int p = tid; p < NS * NT; p += TPB) {
        const int s  = p >> 4;
        const int tl = p & 15;
        float dx = s_tr[tl * 3 + 0] - s_sr[s * 3 + 0];
        float dy = s_tr[tl * 3 + 1] - s_sr[s * 3 + 1];
        float dz = s_tr[tl * 3 + 2] - s_sr[s * 3 + 2];
        float g = 0.f, c1 = 0.f, c2 = 0.f, c3 = 0.f, c4 = 0.f;
        if (t0 + tl != s0 + s) {
            float r2 = dx * dx + dy * dy + dz * dz;
            float rr = sqrtf(r2);
            float E  = NCE * erff(A_ERF * rr);
            float G  = NCG * expf(-0.5f * rr * rr);
            float ir = 1.0f / rr;
            float ir2 = ir * ir,  ir3 = ir2 * ir,  ir4 = ir2 * ir2, ir5 = ir4 * ir;
            float ir6 = ir4 * ir2, ir7 = ir6 * ir, ir8 = ir4 * ir4, ir9 = ir8 * ir;
            g  = E * ir;
            c1 = G * ir2 - E * ir3;
            c2 = 3.0f * E * ir5 - 3.0f * G * ir4 - G * ir2;                       // 2*a2 = 1
            c3 = -15.0f * E * ir7 + 15.0f * G * ir6 + 5.0f * G * ir4 + G * ir2;   // 10*a2=5, 4*a2^2=1
            c4 = 105.0f * E * ir9 - 105.0f * G * ir8 - 35.0f * G * ir6
                 - 7.0f * G * ir4 - G * ir2;                                      // 70a2=35, 28a2^2=7, 8a2^3=1
        }
        float4* op = (float4*)&s_pair[p * 8];
        op[0] = make_float4(g, c1, c2, c3);
        op[1] = make_float4(c4, dx, dy, dz);
    }
    __syncthreads();

    // ---- phase 3: per-(target, channel) accumulation over the source tile ----
    const int tl = tid >> 3;
    const int qc = tid & 7;

    float A0 = 0.f, A1 = 0.f, A2 = 0.f;
    float Eux = 0.f, Euy = 0.f, Euz = 0.f;
    float EQx = 0.f, EQy = 0.f, EQz = 0.f;
    float Efx = 0.f, Efy = 0.f, Efz = 0.f;
    float Qxx = 0.f, Qxy = 0.f, Qxz = 0.f, Qyy = 0.f, Qyz = 0.f, Qzz = 0.f;

#pragma unroll 4
    for (int s = 0; s < NS; s++) {
        const float4 pa = *(const float4*)&s_pair[(s * NT + tl) * 8];
        const float4 pb = *(const float4*)&s_pair[(s * NT + tl) * 8 + 4];
        const float g  = pa.x, c1 = pa.y, c2 = pa.z, c3 = pa.w;
        const float c4 = pb.x, dx = pb.y, dy = pb.z, dz = pb.w;
        const float qs = s_q[s * NQC + qc];
        const float4 uv = *(const float4*)&s_u[(s * NQC + qc) * 4];
        const float ux = uv.x, uy = uv.y, uz = uv.z;
        const float4 qa = *(const float4*)&s_Q[(s * NQC + qc) * 12];
        const float4 qb = *(const float4*)&s_Q[(s * NQC + qc) * 12 + 4];
        const float4 qcv= *(const float4*)&s_Q[(s * NQC + qc) * 12 + 8];
        const float Q00 = qa.x, Q01 = qa.y, Q02 = qa.z;
        const float Q10 = qa.w, Q11 = qb.x, Q12 = qb.y;
        const float Q20 = qb.z, Q21 = qb.w, Q22 = qcv.x;

        const float ud  = fmaf(ux, dx, fmaf(uy, dy, uz * dz));
        const float Qdx = fmaf(Q00, dx, fmaf(Q01, dy, Q02 * dz));
        const float Qdy = fmaf(Q10, dx, fmaf(Q11, dy, Q12 * dz));
        const float Qdz = fmaf(Q20, dx, fmaf(Q21, dy, Q22 * dz));
        const float Qtx = fmaf(Q00, dx, fmaf(Q10, dy, Q20 * dz));
        const float Qty = fmaf(Q01, dx, fmaf(Q11, dy, Q21 * dz));
        const float Qtz = fmaf(Q02, dx, fmaf(Q12, dy, Q22 * dz));
        const float trq = Q00 + Q11 + Q22;
        const float dQd = fmaf(dx, Qdx, fmaf(dy, Qdy, dz * Qdz));
        const float sx = Qdx + Qtx, sy = Qdy + Qty, sz = Qdz + Qtz;

        // potentials at target
        A0 = fmaf(g, qs, A0);
        A1 = fmaf(-c1, ud, A1);
        A2 = fmaf(0.5f * c2, dQd, A2);
        A2 = fmaf(0.5f * c1, trq, A2);

        // E_u (dipole field)
        const float t2u = c2 * ud;
        Eux = fmaf(t2u, dx, fmaf(c1, ux, Eux));
        Euy = fmaf(t2u, dy, fmaf(c1, uy, Euy));
        Euz = fmaf(t2u, dz, fmaf(c1, uz, Euz));

        // E_Q (quadrupole field)
        const float Aq = -0.5f * fmaf(c3, dQd, c2 * trq);
        const float Bq = -0.5f * c2;
        EQx = fmaf(Aq, dx, fmaf(Bq, sx, EQx));
        EQy = fmaf(Aq, dy, fmaf(Bq, sy, EQy));
        EQz = fmaf(Aq, dz, fmaf(Bq, sz, EQz));

        // field from charges
        const float t1q = c1 * qs;
        Efx = fmaf(-t1q, dx, Efx);
        Efy = fmaf(-t1q, dy, Efy);
        Efz = fmaf(-t1q, dz, Efz);

        // QQ (symmetric 3x3)
        const float cA = fmaf(c4, dQd, c3 * trq);
        const float cD = fmaf(c3, dQd, c2 * trq);
        const float hx = c3 * sx, hy = c3 * sy, hz = c3 * sz;
        Qxx = fmaf(cA, dx * dx, Qxx);
        Qxx = fmaf(hx + hx, dx, Qxx);
        Qxx = fmaf(c2, Q00 + Q00, Qxx + cD);
        Qyy = fmaf(cA, dy * dy, Qyy);
        Qyy = fmaf(hy + hy, dy, Qyy);
        Qyy = fmaf(c2, Q11 + Q11, Qyy + cD);
        Qzz = fmaf(cA, dz * dz, Qzz);
        Qzz = fmaf(hz + hz, dz, Qzz);
        Qzz = fmaf(c2, Q22 + Q22, Qzz + cD);
        Qxy = fmaf(cA, dx * dy, Qxy);
        Qxy = fmaf(hx, dy, Qxy);
        Qxy = fmaf(hy, dx, Qxy);
        Qxy = fmaf(c2, Q01 + Q10, Qxy);
        Qxz = fmaf(cA, dx * dz, Qxz);
        Qxz = fmaf(hx, dz, Qxz);
        Qxz = fmaf(hz, dx, Qxz);
        Qxz = fmaf(c2, Q02 + Q20, Qxz);
        Qyz = fmaf(cA, dy * dz, Qyz);
        Qyz = fmaf(hy, dz, Qyz);
        Qyz = fmaf(hz, dy, Qyz);
        Qyz = fmaf(c2, Q12 + Q21, Qyz);
    }

    // ---- accumulate partials into compact L2-resident array (red ops) ----
    const int tqi = (t0 + tl) * NQC + qc;
    const float acc[18] = {A0, A1, A2, Eux, Euy, Euz, EQx, EQy, EQz,
                           Efx, Efy, Efz, Qxx, Qxy, Qxz, Qyy, Qyz, Qzz};
#pragma unroll
    for (int k = 0; k < 18; k++)
        atomicAdd(&g_acc[k * NTQ + tqi], acc[k]);
}

__global__ __launch_bounds__(256)
void finalize_kernel(const float* __restrict__ gq, const float* __restrict__ gu,
                     const float* __restrict__ gQ, const float* __restrict__ gkap,
                     const float* __restrict__ gal, float* __restrict__ out)
{
    const int tqi = blockIdx.x * 256 + threadIdx.x;

    float acc[18];
#pragma unroll
    for (int k = 0; k < 18; k++)
        acc[k] = g_acc[k * NTQ + tqi];
    // re-zero for the next invocation (self-cleaning accumulator)
#pragma unroll
    for (int k = 0; k < 18; k++)
        g_acc[k * NTQ + tqi] = 0.0f;

    const float A0 = acc[0], A1 = acc[1], A2 = acc[2];
    const float Eux = acc[3], Euy = acc[4], Euz = acc[5];
    const float EQx = acc[6], EQy = acc[7], EQz = acc[8];
    const float Efx = acc[9], Efy = acc[10], Efz = acc[11];
    const float Qxx = acc[12], Qxy = acc[13], Qxz = acc[14];
    const float Qyy = acc[15], Qyz = acc[16], Qzz = acc[17];

    const float qv  = gq[tqi];
    const float kap = gkap[tqi];
    const float al  = gal[tqi];
    const float ux = gu[tqi * 3 + 0], uy = gu[tqi * 3 + 1], uz = gu[tqi * 3 + 2];
    const float* Qp = gQ + tqi * 9;

    const float ephi = A0 + A1 + A2;
    out[1 + tqi] = -kap * ephi;                               // q_induced

    const float ex = Efx + Eux + EQx;
    const float ey = Efy + Euy + EQy;
    const float ez = Efz + Euz + EQz;
    out[1 + NTQ + tqi * 3 + 0] = al * ex;                     // u_induced
    out[1 + NTQ + tqi * 3 + 1] = al * ey;
    out[1 + NTQ + tqi * 3 + 2] = al * ez;

    const float qQQ = Qp[0] * Qxx + Qp[4] * Qyy + Qp[8] * Qzz
                    + (Qp[1] + Qp[3]) * Qxy + (Qp[2] + Qp[6]) * Qxz
                    + (Qp[5] + Qp[7]) * Qyz;
    const float uEu = ux * Eux + uy * Euy + uz * Euz;
    const float uEQ = ux * EQx + uy * EQy + uz * EQz;
    const float e2  = ex * ex + ey * ey + ez * ez;

    float pot = 0.5f * A0 * qv + A1 * qv - 0.5f * uEu + qv * A2
              + 0.125f * qQQ - uEQ
              - 0.5f * kap * ephi * ephi
              - 0.5f * al * e2;

    __shared__ float red[256];
    red[threadIdx.x] = pot;
    __syncthreads();
    for (int off = 128; off > 0; off >>= 1) {
        if (threadIdx.x < off) red[threadIdx.x] += red[threadIdx.x + off];
        __syncthreads();
    }
    if (threadIdx.x == 0) atomicAdd(&out[0], red[0]);
}

extern "C" void kernel_launch(void* const* d_in, const int* in_sizes, int n_in,
                              void* d_out, int out_size)
{
    (void)in_sizes; (void)n_in; (void)out_size;
    const float* q     = (const float*)d_in[0];
    const float* r     = (const float*)d_in[1];
    // d_in[2] = cell (zero -> realspace branch), d_in[3] = batch (single graph): unused
    const float* u     = (const float*)d_in[4];
    const float* quad  = (const float*)d_in[5];
    const float* kappa = (const float*)d_in[6];
    const float* alpha = (const float*)d_in[7];
    float* out = (float*)d_out;

    pairs_kernel<<<dim3(N_ATOMS / NT, NCH), TPB>>>(q, r, u, quad, out);
    finalize_kernel<<<NTQ / 256, 256>>>(q, u, quad, kappa, alpha, out);
}

// round 5
// speedup vs baseline: 1.8143x; 1.0300x over previous
#include <cuda_runtime.h>
#include <math.h>

#define N_ATOMS 512
#define NQC     8
#define NT      16      // targets per block
#define NS      16      // sources per chunk
#define NCH     32      // source chunks
#define TPB     128     // NT * NQC
#define NTQ     (N_ATOMS * NQC)   // 4096

// compact accumulators: [18][tq] (288 KB, L2-resident).
// Zero at process start (static init); finalize re-zeroes after reading,
// so every kernel_launch invocation sees a clean array.
__device__ float g_acc[18 * NTQ];

__global__ __launch_bounds__(TPB, 8)
void pairs_kernel(const float* __restrict__ gq, const float* __restrict__ gr,
                  const float* __restrict__ gu, const float* __restrict__ gQ,
                  float* __restrict__ out)
{
    __shared__ __align__(16) float s_sr[NS * 3];
    __shared__ __align__(16) float s_tr[NT * 3];
    __shared__ __align__(16) float s_q [NS * NQC];          // 512 B
    __shared__ __align__(16) float s_u [NS * NQC * 4];      // 2 KB (stride-4 pad)
    __shared__ __align__(16) float s_Q [NS * NQC * 12];     // 6 KB (stride-12 pad)
    __shared__ __align__(16) float s_pair[NS * NT * 8];     // 8 KB {g,c1,c2,c3,c4,dx,dy,dz}

    const int tid = threadIdx.x;
    const int t0  = blockIdx.x * NT;
    const int s0  = blockIdx.y * NS;

    if (blockIdx.x == 0 && blockIdx.y == 0 && tid == 0)
        out[0] = 0.0f;   // pot accumulator, consumed by finalize after this grid completes

    // ---- phase 1: stage source + target data into smem ----
    for (int i = tid; i < NS * 3; i += TPB) s_sr[i] = gr[s0 * 3 + i];
    for (int i = tid; i < NT * 3; i += TPB) s_tr[i] = gr[t0 * 3 + i];
    {
        const float4* src = (const float4*)(gq + s0 * NQC);
        float4* dst = (float4*)s_q;
        for (int i = tid; i < NS * NQC / 4; i += TPB) dst[i] = src[i];
    }
    for (int i = tid; i < NS * NQC; i += TPB) {
        const float* up = gu + (s0 * NQC + i) * 3;
        s_u[i * 4 + 0] = up[0]; s_u[i * 4 + 1] = up[1]; s_u[i * 4 + 2] = up[2];
    }
    for (int i = tid; i < NS * NQC; i += TPB) {
        const float* Qp = gQ + (s0 * NQC + i) * 9;
#pragma unroll
        for (int k = 0; k < 9; k++) s_Q[i * 12 + k] = Qp[k];
    }
    __syncthreads();

    // ---- phase 2: pair scalar kernels (g, D1..D4)*nc and displacement ----
    const float A_ERF = 0.70710678118654752f;                         // 1/sqrt(2)
    const float NCE = (float)(90.4756 / (2.0 * 3.14159265358979323846));
    const float NCG = (float)((90.4756 / (2.0 * 3.14159265358979323846))
                              * 0.79788456080286536);                 // nc * 2a/sqrt(pi)

#pragma unroll
    for (int p = tid; p < NS * NT; p += TPB) {
        const int s  = p >> 4;
        const int tl = p & 15;
        float dx = s_tr[tl * 3 + 0] - s_sr[s * 3 + 0];
        float dy = s_tr[tl * 3 + 1] - s_sr[s * 3 + 1];
        float dz = s_tr[tl * 3 + 2] - s_sr[s * 3 + 2];
        float g = 0.f, c1 = 0.f, c2 = 0.f, c3 = 0.f, c4 = 0.f;
        if (t0 + tl != s0 + s) {
            float r2 = dx * dx + dy * dy + dz * dz;
            float rr = sqrtf(r2);
            float E  = NCE * erff(A_ERF * rr);
            float G  = NCG * expf(-0.5f * rr * rr);
            float ir = 1.0f / rr;
            float ir2 = ir * ir,  ir3 = ir2 * ir,  ir4 = ir2 * ir2, ir5 = ir4 * ir;
            float ir6 = ir4 * ir2, ir7 = ir6 * ir, ir8 = ir4 * ir4, ir9 = ir8 * ir;
            g  = E * ir;
            c1 = G * ir2 - E * ir3;
            c2 = 3.0f * E * ir5 - 3.0f * G * ir4 - G * ir2;                       // 2*a2 = 1
            c3 = -15.0f * E * ir7 + 15.0f * G * ir6 + 5.0f * G * ir4 + G * ir2;   // 10*a2=5, 4*a2^2=1
            c4 = 105.0f * E * ir9 - 105.0f * G * ir8 - 35.0f * G * ir6
                 - 7.0f * G * ir4 - G * ir2;                                      // 70a2=35, 28a2^2=7, 8a2^3=1
        }
        float4* op = (float4*)&s_pair[p * 8];
        op[0] = make_float4(g, c1, c2, c3);
        op[1] = make_float4(c4, dx, dy, dz);
    }
    __syncthreads();

    // ---- phase 3: per-(target, channel) accumulation over the source tile ----
    const int tl = tid >> 3;
    const int qc = tid & 7;

    float A0 = 0.f, A1 = 0.f, A2 = 0.f;
    float Eux = 0.f, Euy = 0.f, Euz = 0.f;
    float EQx = 0.f, EQy = 0.f, EQz = 0.f;
    float Efx = 0.f, Efy = 0.f, Efz = 0.f;
    float Qxx = 0.f, Qxy = 0.f, Qxz = 0.f, Qyy = 0.f, Qyz = 0.f, Qzz = 0.f;

#pragma unroll 4
    for (int s = 0; s < NS; s++) {
        const float4 pa = *(const float4*)&s_pair[(s * NT + tl) * 8];
        const float4 pb = *(const float4*)&s_pair[(s * NT + tl) * 8 + 4];
        const float g  = pa.x, c1 = pa.y, c2 = pa.z, c3 = pa.w;
        const float c4 = pb.x, dx = pb.y, dy = pb.z, dz = pb.w;
        const float qs = s_q[s * NQC + qc];
        const float4 uv = *(const float4*)&s_u[(s * NQC + qc) * 4];
        const float ux = uv.x, uy = uv.y, uz = uv.z;
        const float4 qa = *(const float4*)&s_Q[(s * NQC + qc) * 12];
        const float4 qb = *(const float4*)&s_Q[(s * NQC + qc) * 12 + 4];
        const float4 qcv= *(const float4*)&s_Q[(s * NQC + qc) * 12 + 8];
        const float Q00 = qa.x, Q01 = qa.y, Q02 = qa.z;
        const float Q10 = qa.w, Q11 = qb.x, Q12 = qb.y;
        const float Q20 = qb.z, Q21 = qb.w, Q22 = qcv.x;

        const float ud  = fmaf(ux, dx, fmaf(uy, dy, uz * dz));
        const float Qdx = fmaf(Q00, dx, fmaf(Q01, dy, Q02 * dz));
        const float Qdy = fmaf(Q10, dx, fmaf(Q11, dy, Q12 * dz));
        const float Qdz = fmaf(Q20, dx, fmaf(Q21, dy, Q22 * dz));
        const float Qtx = fmaf(Q00, dx, fmaf(Q10, dy, Q20 * dz));
        const float Qty = fmaf(Q01, dx, fmaf(Q11, dy, Q21 * dz));
        const float Qtz = fmaf(Q02, dx, fmaf(Q12, dy, Q22 * dz));
        const float trq = Q00 + Q11 + Q22;
        const float dQd = fmaf(dx, Qdx, fmaf(dy, Qdy, dz * Qdz));
        const float sx = Qdx + Qtx, sy = Qdy + Qty, sz = Qdz + Qtz;

        // potentials at target
        A0 = fmaf(g, qs, A0);
        A1 = fmaf(-c1, ud, A1);
        A2 = fmaf(0.5f * c2, dQd, A2);
        A2 = fmaf(0.5f * c1, trq, A2);

        // E_u (dipole field)
        const float t2u = c2 * ud;
        Eux = fmaf(t2u, dx, fmaf(c1, ux, Eux));
        Euy = fmaf(t2u, dy, fmaf(c1, uy, Euy));
        Euz = fmaf(t2u, dz, fmaf(c1, uz, Euz));

        // E_Q (quadrupole field)
        const float Aq = -0.5f * fmaf(c3, dQd, c2 * trq);
        const float Bq = -0.5f * c2;
        EQx = fmaf(Aq, dx, fmaf(Bq, sx, EQx));
        EQy = fmaf(Aq, dy, fmaf(Bq, sy, EQy));
        EQz = fmaf(Aq, dz, fmaf(Bq, sz, EQz));

        // field from charges
        const float t1q = c1 * qs;
        Efx = fmaf(-t1q, dx, Efx);
        Efy = fmaf(-t1q, dy, Efy);
        Efz = fmaf(-t1q, dz, Efz);

        // QQ (symmetric 3x3)
        const float cA = fmaf(c4, dQd, c3 * trq);
        const float cD = fmaf(c3, dQd, c2 * trq);
        const float hx = c3 * sx, hy = c3 * sy, hz = c3 * sz;
        Qxx = fmaf(cA, dx * dx, Qxx);
        Qxx = fmaf(hx + hx, dx, Qxx);
        Qxx = fmaf(c2, Q00 + Q00, Qxx + cD);
        Qyy = fmaf(cA, dy * dy, Qyy);
        Qyy = fmaf(hy + hy, dy, Qyy);
        Qyy = fmaf(c2, Q11 + Q11, Qyy + cD);
        Qzz = fmaf(cA, dz * dz, Qzz);
        Qzz = fmaf(hz + hz, dz, Qzz);
        Qzz = fmaf(c2, Q22 + Q22, Qzz + cD);
        Qxy = fmaf(cA, dx * dy, Qxy);
        Qxy = fmaf(hx, dy, Qxy);
        Qxy = fmaf(hy, dx, Qxy);
        Qxy = fmaf(c2, Q01 + Q10, Qxy);
        Qxz = fmaf(cA, dx * dz, Qxz);
        Qxz = fmaf(hx, dz, Qxz);
        Qxz = fmaf(hz, dx, Qxz);
        Qxz = fmaf(c2, Q02 + Q20, Qxz);
        Qyz = fmaf(cA, dy * dz, Qyz);
        Qyz = fmaf(hy, dz, Qyz);
        Qyz = fmaf(hz, dy, Qyz);
        Qyz = fmaf(c2, Q12 + Q21, Qyz);
    }

    // ---- accumulate partials into compact L2-resident array (red ops) ----
    const int tqi = (t0 + tl) * NQC + qc;
    const float acc[18] = {A0, A1, A2, Eux, Euy, Euz, EQx, EQy, EQz,
                           Efx, Efy, Efz, Qxx, Qxy, Qxz, Qyy, Qyz, Qzz};
#pragma unroll
    for (int k = 0; k < 18; k++)
        atomicAdd(&g_acc[k * NTQ + tqi], acc[k]);
}

// one warp per block; grid = NTQ/32 = 128 blocks -> spread over 128 SMs
__global__ __launch_bounds__(32)
void finalize_kernel(const float* __restrict__ gq, const float* __restrict__ gu,
                     const float* __restrict__ gQ, const float* __restrict__ gkap,
                     const float* __restrict__ gal, float* __restrict__ out)
{
    const int tqi = blockIdx.x * 32 + threadIdx.x;

    float acc[18];
#pragma unroll
    for (int k = 0; k < 18; k++)
        acc[k] = g_acc[k * NTQ + tqi];
    // re-zero for the next invocation (self-cleaning accumulator)
#pragma unroll
    for (int k = 0; k < 18; k++)
        g_acc[k * NTQ + tqi] = 0.0f;

    const float A0 = acc[0], A1 = acc[1], A2 = acc[2];
    const float Eux = acc[3], Euy = acc[4], Euz = acc[5];
    const float EQx = acc[6], EQy = acc[7], EQz = acc[8];
    const float Efx = acc[9], Efy = acc[10], Efz = acc[11];
    const float Qxx = acc[12], Qxy = acc[13], Qxz = acc[14];
    const float Qyy = acc[15], Qyz = acc[16], Qzz = acc[17];

    const float qv  = gq[tqi];
    const float kap = gkap[tqi];
    const float al  = gal[tqi];
    const float ux = gu[tqi * 3 + 0], uy = gu[tqi * 3 + 1], uz = gu[tqi * 3 + 2];
    const float* Qp = gQ + tqi * 9;

    const float ephi = A0 + A1 + A2;
    out[1 + tqi] = -kap * ephi;                               // q_induced

    const float ex = Efx + Eux + EQx;
    const float ey = Efy + Euy + EQy;
    const float ez = Efz + Euz + EQz;
    out[1 + NTQ + tqi * 3 + 0] = al * ex;                     // u_induced
    out[1 + NTQ + tqi * 3 + 1] = al * ey;
    out[1 + NTQ + tqi * 3 + 2] = al * ez;

    const float qQQ = Qp[0] * Qxx + Qp[4] * Qyy + Qp[8] * Qzz
                    + (Qp[1] + Qp[3]) * Qxy + (Qp[2] + Qp[6]) * Qxz
                    + (Qp[5] + Qp[7]) * Qyz;
    const float uEu = ux * Eux + uy * Euy + uz * Euz;
    const float uEQ = ux * EQx + uy * EQy + uz * EQz;
    const float e2  = ex * ex + ey * ey + ez * ez;

    float pot = 0.5f * A0 * qv + A1 * qv - 0.5f * uEu + qv * A2
              + 0.125f * qQQ - uEQ
              - 0.5f * kap * ephi * ephi
              - 0.5f * al * e2;

    // warp-shuffle reduction, one atomic per block
#pragma unroll
    for (int off = 16; off > 0; off >>= 1)
        pot += __shfl_xor_sync(0xFFFFFFFFu, pot, off);
    if (threadIdx.x == 0) atomicAdd(&out[0], pot);
}

extern "C" void kernel_launch(void* const* d_in, const int* in_sizes, int n_in,
                              void* d_out, int out_size)
{
    (void)in_sizes; (void)n_in; (void)out_size;
    const float* q     = (const float*)d_in[0];
    const float* r     = (const float*)d_in[1];
    // d_in[2] = cell (zero -> realspace branch), d_in[3] = batch (single graph): unused
    const float* u     = (const float*)d_in[4];
    const float* quad  = (const float*)d_in[5];
    const float* kappa = (const float*)d_in[6];
    const float* alpha = (const float*)d_in[7];
    float* out = (float*)d_out;

    pairs_kernel<<<dim3(N_ATOMS / NT, NCH), TPB>>>(q, r, u, quad, out);
    finalize_kernel<<<NTQ / 32, 32>>>(q, u, quad, kappa, alpha, out);
}